// round 10
// baseline (speedup 1.0000x reference)
#include <cuda_runtime.h>

// Collapsed SimpleAttention: out[b,k] = (mean_s x[b,s,:]) @ Wv[:,k] + bv[k]
// (softmax over the query axis => sum_q att[b,q,s] = 1 => Q/K/att cancel
//  exactly under the mean-pool).
//
// R9: R7 structure (best: 18.9us), with
//  * per-chunk publish flags: consumers accumulate xbar chunk-by-chunk as
//    producers publish, overlapping Phase A with the stage-1 stream
//    (R7 waited for all 74 chunks, serializing 1.3us of L2 reads after it).
//  * Phase B: 4 rotating accumulators (breaks 32-deep FADD chain).
//  * R8's __ldcs + L2-prefetch REVERTED (prefetch injected 16MB of DRAM
//    traffic during the stream = the measured 2.5us regression).

#define BB     8
#define SS     2048
#define DD     1024
#define DKK    512
#define NCHUNK 74                       // stage-1 blocks per batch
#define TOTB   (NCHUNK * BB)            // 592 = 4 * 148 (one balanced wave)

__device__ float g_partial[BB * NCHUNK * DD];   // [b][chunk][d]
__device__ unsigned g_flag[TOTB] = {};          // per-chunk publish flags
__device__ unsigned g_done = 0;

__global__ void __launch_bounds__(256, 4)
fused_kernel(const float* __restrict__ x,
             const float* __restrict__ Wv,
             const float* __restrict__ bv,
             float* __restrict__ out) {
    __shared__ float xbs[DD];           // xbar for this block's batch
    __shared__ float red[4][64];        // GEMM quarter-reduce
    __shared__ int   is_last;

    const int j = blockIdx.x;           // 0..73
    const int b = blockIdx.y;           // 0..7
    const int t = threadIdx.x;

    // ======================= Stage 1: column sum of x ======================
    {
        const int d  = t * 4;
        const int r0 = (j * SS) / NCHUNK;
        const int r1 = ((j + 1) * SS) / NCHUNK;
        const int n  = r1 - r0;

        const float4* xp = reinterpret_cast<const float4*>(
            x + ((size_t)(b * SS + r0)) * DD + d);
        const size_t rs = DD / 4;

        float4 a0 = make_float4(0.f, 0.f, 0.f, 0.f);
        float4 a1 = make_float4(0.f, 0.f, 0.f, 0.f);
        float4 a2 = make_float4(0.f, 0.f, 0.f, 0.f);
        float4 a3 = make_float4(0.f, 0.f, 0.f, 0.f);

        int s = 0;
        for (; s + 8 <= n; s += 8, xp += 8 * rs) {
            const float4 v0 = xp[0 * rs];
            const float4 v1 = xp[1 * rs];
            const float4 v2 = xp[2 * rs];
            const float4 v3 = xp[3 * rs];
            const float4 v4 = xp[4 * rs];
            const float4 v5 = xp[5 * rs];
            const float4 v6 = xp[6 * rs];
            const float4 v7 = xp[7 * rs];
            a0.x += v0.x; a0.y += v0.y; a0.z += v0.z; a0.w += v0.w;
            a1.x += v1.x; a1.y += v1.y; a1.z += v1.z; a1.w += v1.w;
            a2.x += v2.x; a2.y += v2.y; a2.z += v2.z; a2.w += v2.w;
            a3.x += v3.x; a3.y += v3.y; a3.z += v3.z; a3.w += v3.w;
            a0.x += v4.x; a0.y += v4.y; a0.z += v4.z; a0.w += v4.w;
            a1.x += v5.x; a1.y += v5.y; a1.z += v5.z; a1.w += v5.w;
            a2.x += v6.x; a2.y += v6.y; a2.z += v6.z; a2.w += v6.w;
            a3.x += v7.x; a3.y += v7.y; a3.z += v7.z; a3.w += v7.w;
        }
        for (; s < n; s++, xp += rs) {
            const float4 v = *xp;
            a0.x += v.x; a0.y += v.y; a0.z += v.z; a0.w += v.w;
        }
        a0.x += a1.x; a0.y += a1.y; a0.z += a1.z; a0.w += a1.w;
        a2.x += a3.x; a2.y += a3.y; a2.z += a3.z; a2.w += a3.w;
        a0.x += a2.x; a0.y += a2.y; a0.z += a2.z; a0.w += a2.w;

        *reinterpret_cast<float4*>(
            g_partial + ((size_t)(b * NCHUNK + j)) * DD + d) = a0;
    }
    __syncthreads();
    __threadfence();                    // release this chunk's partials
    if (t == 0) atomicExch(&g_flag[b * NCHUNK + j], 1u);  // publish chunk

    if (j >= 8) return;                 // 528 blocks done; 64 continue

    const int ktile = j;                // k range [64*ktile, 64*ktile+64)
    const int kbase = ktile * 64;

    // ===== Phase A: incremental xbar reduce, overlapped with stage 1 =======
    // Consume chunks in fixed order; each is usually already published.
    {
        const volatile unsigned* fl = (const volatile unsigned*)
            (g_flag + b * NCHUNK);
        const float4* p = reinterpret_cast<const float4*>(
            g_partial + (size_t)(b * NCHUNK) * DD) + t;
        const size_t cs = DD / 4;

        float4 a0 = make_float4(0.f, 0.f, 0.f, 0.f);
        float4 a1 = make_float4(0.f, 0.f, 0.f, 0.f);
        float4 a2 = make_float4(0.f, 0.f, 0.f, 0.f);
        float4 a3 = make_float4(0.f, 0.f, 0.f, 0.f);

        int c = 0;
        for (; c + 8 <= NCHUNK; c += 8) {
#pragma unroll
            for (int i = 0; i < 8; i++)
                while (fl[c + i] == 0u) __nanosleep(32);
            __threadfence();            // acquire: order data loads after flags

            const float4 v0 = p[(size_t)(c + 0) * cs];
            const float4 v1 = p[(size_t)(c + 1) * cs];
            const float4 v2 = p[(size_t)(c + 2) * cs];
            const float4 v3 = p[(size_t)(c + 3) * cs];
            const float4 v4 = p[(size_t)(c + 4) * cs];
            const float4 v5 = p[(size_t)(c + 5) * cs];
            const float4 v6 = p[(size_t)(c + 6) * cs];
            const float4 v7 = p[(size_t)(c + 7) * cs];
            a0.x += v0.x; a0.y += v0.y; a0.z += v0.z; a0.w += v0.w;
            a1.x += v1.x; a1.y += v1.y; a1.z += v1.z; a1.w += v1.w;
            a2.x += v2.x; a2.y += v2.y; a2.z += v2.z; a2.w += v2.w;
            a3.x += v3.x; a3.y += v3.y; a3.z += v3.z; a3.w += v3.w;
            a0.x += v4.x; a0.y += v4.y; a0.z += v4.z; a0.w += v4.w;
            a1.x += v5.x; a1.y += v5.y; a1.z += v5.z; a1.w += v5.w;
            a2.x += v6.x; a2.y += v6.y; a2.z += v6.z; a2.w += v6.w;
            a3.x += v7.x; a3.y += v7.y; a3.z += v7.z; a3.w += v7.w;
        }
        for (; c < NCHUNK; c++) {
            while (fl[c] == 0u) __nanosleep(32);
            __threadfence();
            const float4 v = p[(size_t)c * cs];
            a0.x += v.x; a0.y += v.y; a0.z += v.z; a0.w += v.w;
        }
        a0.x += a1.x; a0.y += a1.y; a0.z += a1.z; a0.w += a1.w;
        a2.x += a3.x; a2.y += a3.y; a2.z += a3.z; a2.w += a3.w;
        a0.x += a2.x; a0.y += a2.y; a0.z += a2.z; a0.w += a2.w;

        const float inv = 1.0f / (float)SS;
        a0.x *= inv; a0.y *= inv; a0.z *= inv; a0.w *= inv;
        reinterpret_cast<float4*>(xbs)[t] = a0;
    }
    __syncthreads();

    // ===== Phase B: GEMM slice, 32 independent Wv loads per group, =========
    // ===== 4 rotating accumulators (no 32-deep FADD chain). ================
    {
        const int kk = t & 63;
        const int q  = t >> 6;
        const int d0 = q * 256;
        float c0 = 0.f, c1 = 0.f, c2 = 0.f, c3 = 0.f;
#pragma unroll
        for (int g = 0; g < 8; g++) {
            const int dg = d0 + g * 32;
            float w[32];
#pragma unroll
            for (int i = 0; i < 32; i++)
                w[i] = Wv[(size_t)(dg + i) * DKK + kbase + kk];
#pragma unroll
            for (int i = 0; i < 32; i += 4) {
                c0 += w[i + 0] * xbs[dg + i + 0];
                c1 += w[i + 1] * xbs[dg + i + 1];
                c2 += w[i + 2] * xbs[dg + i + 2];
                c3 += w[i + 3] * xbs[dg + i + 3];
            }
        }
        red[q][kk] = (c0 + c1) + (c2 + c3);
    }
    __syncthreads();

    if (t < 64) {
        out[(size_t)b * DKK + kbase + t] =
            red[0][t] + red[1][t] + red[2][t] + red[3][t] + bv[kbase + t];
    }

    // =================== Flag reset (last consumer block) ==================
    __syncthreads();
    if (t == 0) {
        const unsigned old = atomicAdd(&g_done, 1u);
        is_last = (old == 63u) ? 1 : 0;
    }
    __syncthreads();
    if (is_last) {
        for (int i = t; i < TOTB; i += 256) g_flag[i] = 0u;
        if (t == 0) { g_done = 0; }
        __threadfence();
    }
}

// ---------------------------------------------------------------------------
// Inputs (metadata order): x, Wq, bq, Wk, bk, Wv, bv
// ---------------------------------------------------------------------------
extern "C" void kernel_launch(void* const* d_in, const int* in_sizes, int n_in,
                              void* d_out, int out_size) {
    const float* x  = (const float*)d_in[0];
    const float* Wv = (const float*)d_in[5];
    const float* bv = (const float*)d_in[6];
    float* out = (float*)d_out;

    fused_kernel<<<dim3(NCHUNK, BB), 256>>>(x, Wv, bv, out);
}

// round 11
// speedup vs baseline: 2.9360x; 2.9360x over previous
#include <cuda_runtime.h>

// Collapsed SimpleAttention: out[b,k] = (mean_s x[b,s,:]) @ Wv[:,k] + bv[k]
// (softmax over the query axis => sum_q att[b,q,s] = 1 => Q/K/att cancel
//  exactly under the mean-pool).
//
// R10 = R7 (best: 18.9us) with ONLY local tail changes:
//  * Phase A: 16 loads in flight (was 8).
//  * Phase B: thread owns a k-PAIR (float2 Wv loads) and a 128-d slice ->
//    4 serial load rounds instead of 8; 4 rotating accumulators.
// R9's flag-overlap is reverted (poll storm starved the stream: 49.9us).

#define BB     8
#define SS     2048
#define DD     1024
#define DKK    512
#define NCHUNK 74                       // stage-1 blocks per batch
#define TOTB   (NCHUNK * BB)            // 592 = 4 * 148 (one balanced wave)

__device__ float g_partial[BB * NCHUNK * DD];   // [b][chunk][d]
__device__ unsigned g_cb[BB] = {0};             // per-batch arrival counters
__device__ unsigned g_done = 0;

__device__ __forceinline__ void spin_until(unsigned* ctr, unsigned target) {
    const volatile unsigned* p = (const volatile unsigned*)ctr;
    while (*p != target) __nanosleep(32);
}

__global__ void __launch_bounds__(256, 4)
fused_kernel(const float* __restrict__ x,
             const float* __restrict__ Wv,
             const float* __restrict__ bv,
             float* __restrict__ out) {
    __shared__ float xbs[DD];           // xbar for this block's batch
    __shared__ float red[8][64];        // GEMM slice-reduce (8 d-slices)

    const int j = blockIdx.x;           // 0..73
    const int b = blockIdx.y;           // 0..7
    const int t = threadIdx.x;

    // ======================= Stage 1: column sum of x ======================
    {
        const int d  = t * 4;
        const int r0 = (j * SS) / NCHUNK;
        const int r1 = ((j + 1) * SS) / NCHUNK;
        const int n  = r1 - r0;

        const float4* xp = reinterpret_cast<const float4*>(
            x + ((size_t)(b * SS + r0)) * DD + d);
        const size_t rs = DD / 4;

        float4 a0 = make_float4(0.f, 0.f, 0.f, 0.f);
        float4 a1 = make_float4(0.f, 0.f, 0.f, 0.f);
        float4 a2 = make_float4(0.f, 0.f, 0.f, 0.f);
        float4 a3 = make_float4(0.f, 0.f, 0.f, 0.f);

        int s = 0;
        for (; s + 8 <= n; s += 8, xp += 8 * rs) {
            const float4 v0 = xp[0 * rs];
            const float4 v1 = xp[1 * rs];
            const float4 v2 = xp[2 * rs];
            const float4 v3 = xp[3 * rs];
            const float4 v4 = xp[4 * rs];
            const float4 v5 = xp[5 * rs];
            const float4 v6 = xp[6 * rs];
            const float4 v7 = xp[7 * rs];
            a0.x += v0.x; a0.y += v0.y; a0.z += v0.z; a0.w += v0.w;
            a1.x += v1.x; a1.y += v1.y; a1.z += v1.z; a1.w += v1.w;
            a2.x += v2.x; a2.y += v2.y; a2.z += v2.z; a2.w += v2.w;
            a3.x += v3.x; a3.y += v3.y; a3.z += v3.z; a3.w += v3.w;
            a0.x += v4.x; a0.y += v4.y; a0.z += v4.z; a0.w += v4.w;
            a1.x += v5.x; a1.y += v5.y; a1.z += v5.z; a1.w += v5.w;
            a2.x += v6.x; a2.y += v6.y; a2.z += v6.z; a2.w += v6.w;
            a3.x += v7.x; a3.y += v7.y; a3.z += v7.z; a3.w += v7.w;
        }
        for (; s < n; s++, xp += rs) {
            const float4 v = *xp;
            a0.x += v.x; a0.y += v.y; a0.z += v.z; a0.w += v.w;
        }
        a0.x += a1.x; a0.y += a1.y; a0.z += a1.z; a0.w += a1.w;
        a2.x += a3.x; a2.y += a3.y; a2.z += a3.z; a2.w += a3.w;
        a0.x += a2.x; a0.y += a2.y; a0.z += a2.z; a0.w += a2.w;

        *reinterpret_cast<float4*>(
            g_partial + ((size_t)(b * NCHUNK + j)) * DD + d) = a0;
    }
    __syncthreads();
    __threadfence();                    // release partials
    if (t == 0) atomicAdd(&g_cb[b], 1u);

    if (j >= 8) return;                 // 528 blocks done; 64 continue

    // =============== Wait for THIS batch's 74 partials only ================
    if (t == 0) spin_until(&g_cb[b], NCHUNK);
    __syncthreads();
    __threadfence();                    // acquire

    const int ktile = j;                // k range [64*ktile, 64*ktile+64)
    const int kbase = ktile * 64;

    // ========= Phase A: xbar reduce, 16 loads in flight ====================
    {
        const float4* p = reinterpret_cast<const float4*>(
            g_partial + (size_t)(b * NCHUNK) * DD) + t;
        const size_t cs = DD / 4;

        float4 a0 = make_float4(0.f, 0.f, 0.f, 0.f);
        float4 a1 = make_float4(0.f, 0.f, 0.f, 0.f);
        float4 a2 = make_float4(0.f, 0.f, 0.f, 0.f);
        float4 a3 = make_float4(0.f, 0.f, 0.f, 0.f);
        int c = 0;
        for (; c + 16 <= NCHUNK; c += 16) {
            float4 v[16];
#pragma unroll
            for (int i = 0; i < 16; i++)
                v[i] = p[(size_t)(c + i) * cs];
#pragma unroll
            for (int i = 0; i < 16; i += 4) {
                a0.x += v[i+0].x; a0.y += v[i+0].y; a0.z += v[i+0].z; a0.w += v[i+0].w;
                a1.x += v[i+1].x; a1.y += v[i+1].y; a1.z += v[i+1].z; a1.w += v[i+1].w;
                a2.x += v[i+2].x; a2.y += v[i+2].y; a2.z += v[i+2].z; a2.w += v[i+2].w;
                a3.x += v[i+3].x; a3.y += v[i+3].y; a3.z += v[i+3].z; a3.w += v[i+3].w;
            }
        }
        for (; c + 8 <= NCHUNK; c += 8) {
            float4 v[8];
#pragma unroll
            for (int i = 0; i < 8; i++)
                v[i] = p[(size_t)(c + i) * cs];
#pragma unroll
            for (int i = 0; i < 8; i += 4) {
                a0.x += v[i+0].x; a0.y += v[i+0].y; a0.z += v[i+0].z; a0.w += v[i+0].w;
                a1.x += v[i+1].x; a1.y += v[i+1].y; a1.z += v[i+1].z; a1.w += v[i+1].w;
                a2.x += v[i+2].x; a2.y += v[i+2].y; a2.z += v[i+2].z; a2.w += v[i+2].w;
                a3.x += v[i+3].x; a3.y += v[i+3].y; a3.z += v[i+3].z; a3.w += v[i+3].w;
            }
        }
        for (; c < NCHUNK; c++) {
            const float4 v = p[(size_t)c * cs];
            a0.x += v.x; a0.y += v.y; a0.z += v.z; a0.w += v.w;
        }
        a0.x += a1.x; a0.y += a1.y; a0.z += a1.z; a0.w += a1.w;
        a2.x += a3.x; a2.y += a3.y; a2.z += a3.z; a2.w += a3.w;
        a0.x += a2.x; a0.y += a2.y; a0.z += a2.z; a0.w += a2.w;

        const float inv = 1.0f / (float)SS;
        a0.x *= inv; a0.y *= inv; a0.z *= inv; a0.w *= inv;
        reinterpret_cast<float4*>(xbs)[t] = a0;
    }
    __syncthreads();

    // ===== Phase B: thread owns a k-pair + 128-d slice; 4 load rounds ======
    {
        const int kp  = (t & 31) * 2;   // k pair within tile (0,2,..,62)
        const int dsl = t >> 5;         // 0..7, 128 d each
        const int d0  = dsl * 128;

        float2 c0 = make_float2(0.f, 0.f);
        float2 c1 = make_float2(0.f, 0.f);
        float2 c2 = make_float2(0.f, 0.f);
        float2 c3 = make_float2(0.f, 0.f);
#pragma unroll
        for (int g = 0; g < 4; g++) {
            const int dg = d0 + g * 32;
            float2 w[32];
#pragma unroll
            for (int i = 0; i < 32; i++)
                w[i] = *reinterpret_cast<const float2*>(
                    Wv + (size_t)(dg + i) * DKK + kbase + kp);
#pragma unroll
            for (int i = 0; i < 32; i += 4) {
                const float x0 = xbs[dg + i + 0];
                const float x1 = xbs[dg + i + 1];
                const float x2 = xbs[dg + i + 2];
                const float x3 = xbs[dg + i + 3];
                c0.x += w[i+0].x * x0; c0.y += w[i+0].y * x0;
                c1.x += w[i+1].x * x1; c1.y += w[i+1].y * x1;
                c2.x += w[i+2].x * x2; c2.y += w[i+2].y * x2;
                c3.x += w[i+3].x * x3; c3.y += w[i+3].y * x3;
            }
        }
        red[dsl][kp]     = (c0.x + c1.x) + (c2.x + c3.x);
        red[dsl][kp + 1] = (c0.y + c1.y) + (c2.y + c3.y);
    }
    __syncthreads();

    if (t < 64) {
        float s = bv[kbase + t];
#pragma unroll
        for (int i = 0; i < 8; i++)
            s += red[i][t];
        out[(size_t)b * DKK + kbase + t] = s;
    }

    // ================= Counter reset (last consumer block) =================
    __syncthreads();
    if (t == 0) {
        const unsigned old = atomicAdd(&g_done, 1u);
        if (old == 63u) {               // all 64 consumer blocks finished
#pragma unroll
            for (int i = 0; i < BB; i++) g_cb[i] = 0;
            g_done = 0;
            __threadfence();
        }
    }
}

// ---------------------------------------------------------------------------
// Inputs (metadata order): x, Wq, bq, Wk, bk, Wv, bv
// ---------------------------------------------------------------------------
extern "C" void kernel_launch(void* const* d_in, const int* in_sizes, int n_in,
                              void* d_out, int out_size) {
    const float* x  = (const float*)d_in[0];
    const float* Wv = (const float*)d_in[5];
    const float* bv = (const float*)d_in[6];
    float* out = (float*)d_out;

    fused_kernel<<<dim3(NCHUNK, BB), 256>>>(x, Wv, bv, out);
}